// round 6
// baseline (speedup 1.0000x reference)
#include <cuda_runtime.h>

#define NUM_CLASSES 1000
#define BATCH 8192
#define DD 4096
#define CE_BLOCKS 1024          // 8192 rows / 8 warps per block
#define DENSE_BLOCKS 4000       // 1000 classes * 4 column chunks

// ---- graph-safe scratch (reset by final_kernel each replay) ----
__device__ double g_loss1;
__device__ double g_loss2;
__device__ int    g_flag;
__device__ int    g_offsets[NUM_CLASSES + 1];
__device__ int    g_sorted [BATCH];

__device__ __forceinline__ float tanh_fast(float x) {
    float y;
    asm("tanh.approx.f32 %0, %1;" : "=f"(y) : "f"(x));
    return y;
}

__device__ __forceinline__ void sig_bce(float x, float y, float& sig, float& bce) {
    const float t  = tanh_fast(0.5f * x);
    sig = fmaf(0.5f, t, 0.5f);                         // sigmoid(x)
    const float sp = fmaf(0.5f, fabsf(t), 0.5f);       // sigmoid(|x|)
    bce = fmaxf(x, 0.f) - x * y - __logf(sp);          // stable BCE w/ logits
}

// ---------------------------------------------------------------------------
// One fused kernel:
//   block 0            : prep (hist + scan + counting-sort) -> release flag
//   blocks 1..1024     : cross-entropy (independent of prep)
//   blocks 1025..5024  : dense segment-sum + BCE (acquire flag, then run)
// ---------------------------------------------------------------------------
__global__ __launch_bounds__(256) void main_kernel(
        const float* __restrict__ logits,
        const int*   __restrict__ target,
        const float* __restrict__ dense_out,
        const float* __restrict__ dense_labels,
        float* __restrict__ out_ds,
        float* __restrict__ out_ta) {

    if (blockIdx.x == 0) {
        // ============================ PREP ================================
        __shared__ int s_cnt[1024];
        __shared__ int s_wsum[8];
        const int tid = threadIdx.x;

        #pragma unroll
        for (int b = tid; b < 1024; b += 256) s_cnt[b] = 0;
        __syncthreads();

        #pragma unroll 1
        for (int k = 0; k < 32; ++k)
            atomicAdd(&s_cnt[target[tid + k * 256]], 1);
        __syncthreads();

        // 4 bins per thread -> block-wide exclusive scan
        const int b0 = 4 * tid;
        const int c0 = s_cnt[b0], c1 = s_cnt[b0 + 1], c2 = s_cnt[b0 + 2], c3 = s_cnt[b0 + 3];
        const int i0 = c0, i1 = i0 + c1, i2 = i1 + c2, i3 = i2 + c3;
        const int tot = i3;
        int isc = tot;
        const int lane = tid & 31, wid = tid >> 5;
        #pragma unroll
        for (int o = 1; o < 32; o <<= 1) {
            const int v = __shfl_up_sync(0xffffffffu, isc, o);
            if (lane >= o) isc += v;
        }
        if (lane == 31) s_wsum[wid] = isc;
        __syncthreads();
        if (tid < 8) {
            int ws = s_wsum[tid];
            #pragma unroll
            for (int o = 1; o < 8; o <<= 1) {
                const int v = __shfl_up_sync(0xffu, ws, o);
                if (tid >= o) ws += v;
            }
            s_wsum[tid] = ws;
        }
        __syncthreads();
        const int excl = isc - tot + (wid ? s_wsum[wid - 1] : 0);

        const int incl0 = excl + i0, incl1 = excl + i1, incl2 = excl + i2, incl3 = excl + i3;
        if (b0     < NUM_CLASSES) { g_offsets[b0 + 1] = incl0; out_ta[b0]     = (float)c0; }
        if (b0 + 1 < NUM_CLASSES) { g_offsets[b0 + 2] = incl1; out_ta[b0 + 1] = (float)c1; }
        if (b0 + 2 < NUM_CLASSES) { g_offsets[b0 + 3] = incl2; out_ta[b0 + 2] = (float)c2; }
        if (b0 + 3 < NUM_CLASSES) { g_offsets[b0 + 4] = incl3; out_ta[b0 + 3] = (float)c3; }
        if (tid == 0) g_offsets[0] = 0;

        // cursors (exclusive) reuse s_cnt
        s_cnt[b0]     = incl0 - c0;
        s_cnt[b0 + 1] = incl1 - c1;
        s_cnt[b0 + 2] = incl2 - c2;
        s_cnt[b0 + 3] = incl3 - c3;
        __syncthreads();

        // counting-sort scatter (order within class irrelevant)
        #pragma unroll 1
        for (int k = 0; k < 32; ++k) {
            const int i = tid + k * 256;
            const int p = atomicAdd(&s_cnt[target[i]], 1);
            g_sorted[p] = i;
        }
        __threadfence();
        __syncthreads();
        if (tid == 0)
            asm volatile("st.release.gpu.u32 [%0], %1;" :: "l"(&g_flag), "r"(1) : "memory");

    } else if (blockIdx.x <= CE_BLOCKS) {
        // ======================= CROSS-ENTROPY ============================
        const int warp = threadIdx.x >> 5;
        const int lane = threadIdx.x & 31;
        const int r    = (blockIdx.x - 1) * 8 + warp;
        const float4* row = (const float4*)(logits + (size_t)r * NUM_CLASSES);

        float m = -1e30f, ssum = 0.f;
        #pragma unroll
        for (int k = 0; k < 8; ++k) {
            const int idx = k * 32 + lane;           // float4 index, 250 valid
            if (idx < NUM_CLASSES / 4) {
                const float4 v = row[idx];
                const float mv = fmaxf(fmaxf(v.x, v.y), fmaxf(v.z, v.w));
                const float mn = fmaxf(m, mv);
                ssum = ssum * __expf(m - mn)
                     + __expf(v.x - mn) + __expf(v.y - mn)
                     + __expf(v.z - mn) + __expf(v.w - mn);
                m = mn;
            }
        }
        #pragma unroll
        for (int off = 16; off; off >>= 1) {
            const float mo = __shfl_xor_sync(0xffffffffu, m, off);
            const float so = __shfl_xor_sync(0xffffffffu, ssum, off);
            const float mn = fmaxf(m, mo);
            ssum = ssum * __expf(m - mn) + so * __expf(mo - mn);
            m = mn;
        }

        __shared__ float part[8];
        if (lane == 0)
            part[warp] = (__logf(ssum) + m)
                       - logits[(size_t)r * NUM_CLASSES + target[r]];
        __syncthreads();
        if (threadIdx.x == 0) {
            float bs = 0.f;
            #pragma unroll
            for (int w = 0; w < 8; ++w) bs += part[w];
            atomicAdd(&g_loss1, (double)bs);
        }

    } else {
        // ===================== DENSE SEGSUM + BCE =========================
        const int b    = blockIdx.x - 1 - CE_BLOCKS;
        const int c    = b >> 2;
        const int col4 = (b & 3) * 256 + threadIdx.x;     // float4 idx 0..1023

        // load labels early (independent of prep)
        const float4 y = ((const float4*)(dense_labels + (size_t)c * DD))[col4];

        __shared__ int s_bounds[2];
        __shared__ int s_rows[64];

        if (threadIdx.x == 0) {
            int f;
            do {
                asm volatile("ld.acquire.gpu.u32 %0, [%1];" : "=r"(f) : "l"(&g_flag) : "memory");
                if (!f) __nanosleep(200);
            } while (!f);
            s_bounds[0] = g_offsets[c];
            s_bounds[1] = g_offsets[c + 1];
        }
        __syncthreads();
        const int s = s_bounds[0];
        const int n = s_bounds[1] - s;
        if (threadIdx.x < n && threadIdx.x < 64)
            s_rows[threadIdx.x] = g_sorted[s + threadIdx.x];
        __syncthreads();

        float4 acc = make_float4(0.f, 0.f, 0.f, 0.f);
        float  lsum = 0.f;

        int i = 0;
        for (; i + 2 <= n; i += 2) {
            const int r0 = (i     < 64) ? s_rows[i]     : g_sorted[s + i];
            const int r1 = (i + 1 < 64) ? s_rows[i + 1] : g_sorted[s + i + 1];
            const float4 x0 = ((const float4*)(dense_out + (size_t)r0 * DD))[col4];
            const float4 x1 = ((const float4*)(dense_out + (size_t)r1 * DD))[col4];
            float sg, bc;
            sig_bce(x0.x, y.x, sg, bc); acc.x += sg; lsum += bc;
            sig_bce(x0.y, y.y, sg, bc); acc.y += sg; lsum += bc;
            sig_bce(x0.z, y.z, sg, bc); acc.z += sg; lsum += bc;
            sig_bce(x0.w, y.w, sg, bc); acc.w += sg; lsum += bc;
            sig_bce(x1.x, y.x, sg, bc); acc.x += sg; lsum += bc;
            sig_bce(x1.y, y.y, sg, bc); acc.y += sg; lsum += bc;
            sig_bce(x1.z, y.z, sg, bc); acc.z += sg; lsum += bc;
            sig_bce(x1.w, y.w, sg, bc); acc.w += sg; lsum += bc;
        }
        if (i < n) {
            const int r0 = (i < 64) ? s_rows[i] : g_sorted[s + i];
            const float4 x0 = ((const float4*)(dense_out + (size_t)r0 * DD))[col4];
            float sg, bc;
            sig_bce(x0.x, y.x, sg, bc); acc.x += sg; lsum += bc;
            sig_bce(x0.y, y.y, sg, bc); acc.y += sg; lsum += bc;
            sig_bce(x0.z, y.z, sg, bc); acc.z += sg; lsum += bc;
            sig_bce(x0.w, y.w, sg, bc); acc.w += sg; lsum += bc;
        }

        float* dst = out_ds + (size_t)c * DD + (size_t)col4 * 4;  // 4B-aligned only
        dst[0] = acc.x; dst[1] = acc.y; dst[2] = acc.z; dst[3] = acc.w;

        #pragma unroll
        for (int o = 16; o; o >>= 1)
            lsum += __shfl_xor_sync(0xffffffffu, lsum, o);
        __shared__ float wpart[8];
        const int wid = threadIdx.x >> 5, lane = threadIdx.x & 31;
        if (lane == 0) wpart[wid] = lsum;
        __syncthreads();
        if (threadIdx.x == 0) {
            float bs = 0.f;
            #pragma unroll
            for (int w = 0; w < 8; ++w) bs += wpart[w];
            atomicAdd(&g_loss2, (double)bs);
        }
    }
}

// ---------------------------------------------------------------------------
// Combine losses; read-then-reset scratch so every graph replay starts clean.
// ---------------------------------------------------------------------------
__global__ void final_kernel(float* __restrict__ out) {
    const double l1 = g_loss1 / (double)BATCH;
    const double l2 = g_loss2 / ((double)BATCH * (double)DD);
    out[0] = (float)(0.5 * l1 + 0.5 * l2);
    g_loss1 = 0.0;
    g_loss2 = 0.0;
    g_flag  = 0;
}

// ---------------------------------------------------------------------------
extern "C" void kernel_launch(void* const* d_in, const int* in_sizes, int n_in,
                              void* d_out, int out_size) {
    const float* logits       = (const float*)d_in[0];
    const float* dense_out    = (const float*)d_in[1];
    const int*   target       = (const int*)  d_in[2];
    const float* dense_labels = (const float*)d_in[3];

    float* out    = (float*)d_out;
    float* out_ds = out + 1;
    float* out_ta = out + 1 + (size_t)NUM_CLASSES * DD;

    main_kernel<<<1 + CE_BLOCKS + DENSE_BLOCKS, 256>>>(
        logits, target, dense_out, dense_labels, out_ds, out_ta);
    final_kernel<<<1, 1>>>(out);
}